// round 8
// baseline (speedup 1.0000x reference)
#include <cuda_runtime.h>
#include <math.h>

// ---------------------------------------------------------------------------
// Problem constants (shapes fixed by the dataset)
// ---------------------------------------------------------------------------
#define NMAX 100000
#define EMAX 1200000
#define MAX_SCAN_BLOCKS 128   // ceil(NMAX/1024) = 98 < 128

// ---------------------------------------------------------------------------
// Scratch (static __device__ arrays; no allocations allowed)
// ---------------------------------------------------------------------------
__device__ float g_h0[NMAX * 128];   // embedding concat  [N,128]
__device__ float g_agg[NMAX * 128];  // aggregation buffer (reused, layer1 uses 64)
__device__ float g_x1[NMAX * 64];    // layer0 pre-BN
__device__ float g_h1[NMAX * 64];    // layer0 output
__device__ float g_x2[NMAX * 64];    // layer1 pre-BN
__device__ float g_h2[NMAX * 64];    // layer1 output
__device__ float g_xf[NMAX * 64];    // fc pre-BN

__device__ int g_deg[NMAX];
__device__ int g_rowstart[NMAX];
__device__ int g_cursor[NMAX];
__device__ int g_csr[EMAX];
__device__ int g_blocksum[MAX_SCAN_BLOCKS];
__device__ int g_blockoff[MAX_SCAN_BLOCKS];

__device__ float g_red[128];  // [0..64) sum, [64..128) sumsq
__device__ float g_bnA[64];
__device__ float g_bnB[64];

// ---------------------------------------------------------------------------
// f32x2 helpers (sm_103a packed FFMA2 — only reachable via PTX)
// ---------------------------------------------------------------------------
__device__ __forceinline__ unsigned long long pack2(float lo, float hi) {
    unsigned long long r;
    asm("mov.b64 %0, {%1, %2};" : "=l"(r) : "r"(__float_as_uint(lo)), "r"(__float_as_uint(hi)));
    return r;
}
__device__ __forceinline__ void unpack2(unsigned long long v, float& lo, float& hi) {
    unsigned int a, b;
    asm("mov.b64 {%0, %1}, %2;" : "=r"(a), "=r"(b) : "l"(v));
    lo = __uint_as_float(a);
    hi = __uint_as_float(b);
}
__device__ __forceinline__ unsigned long long ffma2(unsigned long long a,
                                                    unsigned long long b,
                                                    unsigned long long c) {
    unsigned long long d;
    asm("fma.rn.f32x2 %0, %1, %2, %3;" : "=l"(d) : "l"(a), "l"(b), "l"(c));
    return d;
}
__device__ __forceinline__ float lrelu(float v) { return v > 0.f ? v : 0.01f * v; }

// ---------------------------------------------------------------------------
// Embedding concat: h0[node] = [emb_deg[deg], emb_lab[lab]]  (32 lanes/node)
// ---------------------------------------------------------------------------
__global__ void __launch_bounds__(256) k_init(const int* __restrict__ nd,
                                              const int* __restrict__ nl,
                                              const float* __restrict__ ed,
                                              const float* __restrict__ el, int N) {
    int g = blockIdx.x * 256 + threadIdx.x;
    int node = g >> 5, lane = g & 31;
    if (node >= N) return;
    float4 v;
    if (lane < 16)
        v = reinterpret_cast<const float4*>(ed + (size_t)nd[node] * 64)[lane];
    else
        v = reinterpret_cast<const float4*>(el + (size_t)nl[node] * 64)[lane - 16];
    reinterpret_cast<float4*>(g_h0 + (size_t)node * 128)[lane] = v;
}

// ---------------------------------------------------------------------------
// CSR build: zero deg -> count -> scan -> fill
// ---------------------------------------------------------------------------
__global__ void k_zero_deg(int N) {
    int i = blockIdx.x * blockDim.x + threadIdx.x;
    if (i < N) g_deg[i] = 0;
}
__global__ void k_count(const int* __restrict__ ei, int E) {
    int e = blockIdx.x * blockDim.x + threadIdx.x;
    if (e < E) atomicAdd(&g_deg[ei[E + e]], 1);
}
__global__ void __launch_bounds__(1024) k_scan1(int N) {
    __shared__ int s[1024];
    int t = threadIdx.x;
    int i = blockIdx.x * 1024 + t;
    int v = (i < N) ? g_deg[i] : 0;
    s[t] = v;
    __syncthreads();
#pragma unroll
    for (int off = 1; off < 1024; off <<= 1) {
        int a = (t >= off) ? s[t - off] : 0;
        __syncthreads();
        s[t] += a;
        __syncthreads();
    }
    if (i < N) g_rowstart[i] = s[t] - v;  // exclusive within block
    if (t == 1023) g_blocksum[blockIdx.x] = s[1023];
}
__global__ void k_scan2(int nb) {
    // single thread; nb <= MAX_SCAN_BLOCKS, trivially bounded
    int acc = 0;
    for (int b = 0; b < nb; b++) {
        g_blockoff[b] = acc;
        acc += g_blocksum[b];
    }
}
__global__ void __launch_bounds__(1024) k_scan3(int N) {
    int i = blockIdx.x * 1024 + threadIdx.x;
    if (i < N) {
        int r = g_rowstart[i] + g_blockoff[blockIdx.x];
        g_rowstart[i] = r;
        g_cursor[i] = r;
    }
}
__global__ void k_fill(const int* __restrict__ ei, int E) {
    int e = blockIdx.x * blockDim.x + threadIdx.x;
    if (e < E) {
        int src = ei[e];
        int dst = ei[E + e];
        int p = atomicAdd(&g_cursor[dst], 1);
        g_csr[p] = src;
    }
}

// ---------------------------------------------------------------------------
// Segment-sum aggregation (warp per node, gather-based, no float atomics)
// ---------------------------------------------------------------------------
template <int D>
__global__ void __launch_bounds__(256) k_agg(const float* __restrict__ hin,
                                             float* __restrict__ aggout, int N) {
    int g = blockIdx.x * 256 + threadIdx.x;
    int node = g >> 5, lane = g & 31;
    if (node >= N) return;
    int s = g_rowstart[node];
    int d = g_deg[node];
    if (D == 128) {
        float4 acc = make_float4(0.f, 0.f, 0.f, 0.f);
        for (int i = 0; i < d; i++) {
            int src = g_csr[s + i];
            float4 r = reinterpret_cast<const float4*>(hin + (size_t)src * 128)[lane];
            acc.x += r.x; acc.y += r.y; acc.z += r.z; acc.w += r.w;
        }
        reinterpret_cast<float4*>(aggout + (size_t)node * 128)[lane] = acc;
    } else {
        float2 acc = make_float2(0.f, 0.f);
        for (int i = 0; i < d; i++) {
            int src = g_csr[s + i];
            float2 r = reinterpret_cast<const float2*>(hin + (size_t)src * 64)[lane];
            acc.x += r.x; acc.y += r.y;
        }
        reinterpret_cast<float2*>(aggout + (size_t)node * 64)[lane] = acc;
    }
}

// ---------------------------------------------------------------------------
// BN reduction helpers
// ---------------------------------------------------------------------------
__global__ void k_zero_red() {
    if (threadIdx.x < 128) g_red[threadIdx.x] = 0.f;
}
__global__ void k_bn_final(const float* __restrict__ gam, const float* __restrict__ bet,
                           float invN) {
    int c = threadIdx.x;  // 64 threads
    float mean = g_red[c] * invN;
    float var = g_red[64 + c] * invN - mean * mean;
    float a = gam[c] * rsqrtf(var + 1e-5f);
    g_bnA[c] = a;
    g_bnB[c] = bet[c] - mean * a;
}
__global__ void __launch_bounds__(256) k_apply(const float* __restrict__ x,
                                               float* __restrict__ h, int total) {
    int i = blockIdx.x * 256 + threadIdx.x;
    if (i < total) {
        int c = i & 63;
        h[i] = lrelu(fmaf(x[i], g_bnA[c], g_bnB[c]));
    }
}

// ---------------------------------------------------------------------------
// Fused GIN MLP:  x = (1+eps)*h + agg ; hid = lrelu(x@W1+b1) ; out = hid@W2+b2
// Writes pre-BN out and accumulates per-channel sum/sumsq for BatchNorm.
// Block = 64 nodes, 256 threads. Register tile: 8 nodes (4 f32x2 pairs) x CT chans.
// ---------------------------------------------------------------------------
template <int K, int H, int M>
__global__ void __launch_bounds__(256) k_mlp(const float* __restrict__ hin,
                                             const float* __restrict__ agg,
                                             const float* __restrict__ W1,
                                             const float* __restrict__ b1,
                                             const float* __restrict__ W2,
                                             const float* __restrict__ b2,
                                             const float* __restrict__ epsp,
                                             float* __restrict__ xout, int N) {
    constexpr int NP = 66;  // padded node stride (bank-friendly, 8B-aligned rows)
    extern __shared__ float sm[];
    float* xs = sm;               // [K][NP] transposed input tile
    float* hs = xs + K * NP;      // [H][NP] transposed hidden tile
    float* W1s = hs + H * NP;     // [K][H]
    float* W2s = W1s + K * H;     // [H][M]
    float* sred = W2s + H * M;    // [2*M]

    int tid = threadIdx.x;
    int node0 = blockIdx.x * 64;
    float eps1 = 1.0f + epsp[0];

    for (int i = tid; i < K * H; i += 256) W1s[i] = W1[i];
    for (int i = tid; i < H * M; i += 256) W2s[i] = W2[i];
    if (tid < 2 * M) sred[tid] = 0.f;
    for (int i = tid; i < 64 * K; i += 256) {
        int n = i / K, k = i - n * K;
        int node = node0 + n;
        float v = 0.f;
        if (node < N) v = fmaf(eps1, hin[(size_t)node * K + k], agg[(size_t)node * K + k]);
        xs[k * NP + n] = v;
    }
    __syncthreads();

    int cg = tid & 31;
    int ng = tid >> 5;
    int n0 = ng * 8;

    // ---- stage 1: x @ W1 -> hidden (lrelu), CT1 = H/32 channels/thread ----
    constexpr int CT1 = H / 32;
    {
        int c0 = cg * CT1;
        unsigned long long acc[4][CT1];
#pragma unroll
        for (int j = 0; j < CT1; j++) {
            unsigned long long bb = pack2(b1[c0 + j], b1[c0 + j]);
#pragma unroll
            for (int p = 0; p < 4; p++) acc[p][j] = bb;
        }
#pragma unroll 4
        for (int k = 0; k < K; k++) {
            const unsigned long long* ap =
                reinterpret_cast<const unsigned long long*>(xs + k * NP + n0);
            unsigned long long a0 = ap[0], a1 = ap[1], a2 = ap[2], a3 = ap[3];
#pragma unroll
            for (int j = 0; j < CT1; j++) {
                float w = W1s[k * H + c0 + j];
                unsigned long long ww = pack2(w, w);
                acc[0][j] = ffma2(a0, ww, acc[0][j]);
                acc[1][j] = ffma2(a1, ww, acc[1][j]);
                acc[2][j] = ffma2(a2, ww, acc[2][j]);
                acc[3][j] = ffma2(a3, ww, acc[3][j]);
            }
        }
#pragma unroll
        for (int j = 0; j < CT1; j++)
#pragma unroll
            for (int p = 0; p < 4; p++) {
                float lo, hi;
                unpack2(acc[p][j], lo, hi);
                float2 st = make_float2(lrelu(lo), lrelu(hi));
                *reinterpret_cast<float2*>(hs + (c0 + j) * NP + n0 + 2 * p) = st;
            }
    }
    __syncthreads();

    // ---- stage 2: hidden @ W2 -> out, CT2 = M/32 channels/thread ----
    constexpr int CT2 = M / 32;
    {
        int c0 = cg * CT2;
        unsigned long long acc[4][CT2];
#pragma unroll
        for (int j = 0; j < CT2; j++) {
            unsigned long long bb = pack2(b2[c0 + j], b2[c0 + j]);
#pragma unroll
            for (int p = 0; p < 4; p++) acc[p][j] = bb;
        }
#pragma unroll 4
        for (int k = 0; k < H; k++) {
            const unsigned long long* ap =
                reinterpret_cast<const unsigned long long*>(hs + k * NP + n0);
            unsigned long long a0 = ap[0], a1 = ap[1], a2 = ap[2], a3 = ap[3];
#pragma unroll
            for (int j = 0; j < CT2; j++) {
                float w = W2s[k * M + c0 + j];
                unsigned long long ww = pack2(w, w);
                acc[0][j] = ffma2(a0, ww, acc[0][j]);
                acc[1][j] = ffma2(a1, ww, acc[1][j]);
                acc[2][j] = ffma2(a2, ww, acc[2][j]);
                acc[3][j] = ffma2(a3, ww, acc[3][j]);
            }
        }
        float lsum[CT2], lsq[CT2];
#pragma unroll
        for (int j = 0; j < CT2; j++) { lsum[j] = 0.f; lsq[j] = 0.f; }
#pragma unroll
        for (int p = 0; p < 4; p++) {
            int nA = node0 + n0 + 2 * p;
            float vlo[CT2], vhi[CT2];
#pragma unroll
            for (int j = 0; j < CT2; j++) unpack2(acc[p][j], vlo[j], vhi[j]);
            if (nA < N) {
                float2 st = make_float2(vlo[0], vlo[1]);
                *reinterpret_cast<float2*>(xout + (size_t)nA * M + c0) = st;
#pragma unroll
                for (int j = 0; j < CT2; j++) { lsum[j] += vlo[j]; lsq[j] += vlo[j] * vlo[j]; }
            }
            if (nA + 1 < N) {
                float2 st = make_float2(vhi[0], vhi[1]);
                *reinterpret_cast<float2*>(xout + (size_t)(nA + 1) * M + c0) = st;
#pragma unroll
                for (int j = 0; j < CT2; j++) { lsum[j] += vhi[j]; lsq[j] += vhi[j] * vhi[j]; }
            }
        }
#pragma unroll
        for (int j = 0; j < CT2; j++) {
            atomicAdd(&sred[c0 + j], lsum[j]);
            atomicAdd(&sred[M + c0 + j], lsq[j]);
        }
    }
    __syncthreads();
    if (tid < 2 * M) atomicAdd(&g_red[tid], sred[tid]);
}

// ---------------------------------------------------------------------------
// FC head GEMM: concat(h0,h1,h2) [256] @ fc_w1 [256,64] + b -> xf, + BN sums
// ---------------------------------------------------------------------------
__global__ void __launch_bounds__(256) k_fc(const float* __restrict__ h0,
                                            const float* __restrict__ h1,
                                            const float* __restrict__ h2,
                                            const float* __restrict__ W,
                                            const float* __restrict__ b,
                                            float* __restrict__ xout, int N) {
    constexpr int K = 256, M = 64, NP = 66, CT = 2;
    extern __shared__ float sm[];
    float* xs = sm;              // [K][NP]
    float* Ws = xs + K * NP;     // [K][M]
    float* sred = Ws + K * M;    // [2*M]

    int tid = threadIdx.x;
    int node0 = blockIdx.x * 64;

    for (int i = tid; i < K * M; i += 256) Ws[i] = W[i];
    if (tid < 2 * M) sred[tid] = 0.f;
    for (int i = tid; i < 64 * K; i += 256) {
        int n = i >> 8, k = i & 255;
        int node = node0 + n;
        float v = 0.f;
        if (node < N) {
            if (k < 128) v = h0[(size_t)node * 128 + k];
            else if (k < 192) v = h1[(size_t)node * 64 + (k - 128)];
            else v = h2[(size_t)node * 64 + (k - 192)];
        }
        xs[k * NP + n] = v;
    }
    __syncthreads();

    int cg = tid & 31;
    int ng = tid >> 5;
    int n0 = ng * 8;
    int c0 = cg * CT;

    unsigned long long acc[4][CT];
#pragma unroll
    for (int j = 0; j < CT; j++) {
        unsigned long long bb = pack2(b[c0 + j], b[c0 + j]);
#pragma unroll
        for (int p = 0; p < 4; p++) acc[p][j] = bb;
    }
#pragma unroll 4
    for (int k = 0; k < K; k++) {
        const unsigned long long* ap =
            reinterpret_cast<const unsigned long long*>(xs + k * NP + n0);
        unsigned long long a0 = ap[0], a1 = ap[1], a2 = ap[2], a3 = ap[3];
#pragma unroll
        for (int j = 0; j < CT; j++) {
            float w = Ws[k * M + c0 + j];
            unsigned long long ww = pack2(w, w);
            acc[0][j] = ffma2(a0, ww, acc[0][j]);
            acc[1][j] = ffma2(a1, ww, acc[1][j]);
            acc[2][j] = ffma2(a2, ww, acc[2][j]);
            acc[3][j] = ffma2(a3, ww, acc[3][j]);
        }
    }
    float lsum[CT], lsq[CT];
#pragma unroll
    for (int j = 0; j < CT; j++) { lsum[j] = 0.f; lsq[j] = 0.f; }
#pragma unroll
    for (int p = 0; p < 4; p++) {
        int nA = node0 + n0 + 2 * p;
        float vlo[CT], vhi[CT];
#pragma unroll
        for (int j = 0; j < CT; j++) unpack2(acc[p][j], vlo[j], vhi[j]);
        if (nA < N) {
            *reinterpret_cast<float2*>(xout + (size_t)nA * M + c0) = make_float2(vlo[0], vlo[1]);
#pragma unroll
            for (int j = 0; j < CT; j++) { lsum[j] += vlo[j]; lsq[j] += vlo[j] * vlo[j]; }
        }
        if (nA + 1 < N) {
            *reinterpret_cast<float2*>(xout + (size_t)(nA + 1) * M + c0) = make_float2(vhi[0], vhi[1]);
#pragma unroll
            for (int j = 0; j < CT; j++) { lsum[j] += vhi[j]; lsq[j] += vhi[j] * vhi[j]; }
        }
    }
#pragma unroll
    for (int j = 0; j < CT; j++) {
        atomicAdd(&sred[c0 + j], lsum[j]);
        atomicAdd(&sred[M + c0 + j], lsq[j]);
    }
    __syncthreads();
    if (tid < 2 * 64) atomicAdd(&g_red[tid], sred[tid]);
}

// ---------------------------------------------------------------------------
// Final: BN-apply + lrelu + dot(fc_w2) + sigmoid  (warp per node)
// ---------------------------------------------------------------------------
__global__ void __launch_bounds__(256) k_final(const float* __restrict__ xf,
                                               const float* __restrict__ w2,
                                               const float* __restrict__ b2,
                                               float* __restrict__ out, int N) {
    int g = blockIdx.x * 256 + threadIdx.x;
    int node = g >> 5, lane = g & 31;
    if (node >= N) return;
    int c0 = lane, c1 = lane + 32;
    float v0 = lrelu(fmaf(xf[(size_t)node * 64 + c0], g_bnA[c0], g_bnB[c0]));
    float v1 = lrelu(fmaf(xf[(size_t)node * 64 + c1], g_bnA[c1], g_bnB[c1]));
    float p = v0 * w2[c0] + v1 * w2[c1];
#pragma unroll
    for (int o = 16; o > 0; o >>= 1) p += __shfl_xor_sync(0xffffffffu, p, o);
    if (lane == 0) out[node] = 1.0f / (1.0f + expf(-(p + b2[0])));
}

// ---------------------------------------------------------------------------
// Launch
// ---------------------------------------------------------------------------
extern "C" void kernel_launch(void* const* d_in, const int* in_sizes, int n_in,
                              void* d_out, int out_size) {
    const int* node_deg = (const int*)d_in[0];
    const int* node_lab = (const int*)d_in[1];
    const int* ei       = (const int*)d_in[2];
    const float* emb_deg = (const float*)d_in[3];
    const float* emb_lab = (const float*)d_in[4];
    const float* l0_w1 = (const float*)d_in[5];
    const float* l0_b1 = (const float*)d_in[6];
    const float* l0_w2 = (const float*)d_in[7];
    const float* l0_b2 = (const float*)d_in[8];
    const float* l0_eps = (const float*)d_in[9];
    const float* bn0_g = (const float*)d_in[10];
    const float* bn0_b = (const float*)d_in[11];
    const float* l1_w1 = (const float*)d_in[12];
    const float* l1_b1 = (const float*)d_in[13];
    const float* l1_w2 = (const float*)d_in[14];
    const float* l1_b2 = (const float*)d_in[15];
    const float* l1_eps = (const float*)d_in[16];
    const float* bn1_g = (const float*)d_in[17];
    const float* bn1_b = (const float*)d_in[18];
    const float* fc_w1 = (const float*)d_in[19];
    const float* fc_b1 = (const float*)d_in[20];
    const float* fc_bn_g = (const float*)d_in[21];
    const float* fc_bn_b = (const float*)d_in[22];
    const float* fc_w2 = (const float*)d_in[23];
    const float* fc_b2 = (const float*)d_in[24];
    float* out = (float*)d_out;

    int N = in_sizes[0];
    int E = in_sizes[2] / 2;
    if (N > NMAX) N = NMAX;
    if (E > EMAX) E = EMAX;

    // Scratch pointers from symbols (no allocation)
    float *h0p, *aggp, *x1p, *h1p, *x2p, *h2p, *xfp;
    cudaGetSymbolAddress((void**)&h0p, g_h0);
    cudaGetSymbolAddress((void**)&aggp, g_agg);
    cudaGetSymbolAddress((void**)&x1p, g_x1);
    cudaGetSymbolAddress((void**)&h1p, g_h1);
    cudaGetSymbolAddress((void**)&x2p, g_x2);
    cudaGetSymbolAddress((void**)&h2p, g_h2);
    cudaGetSymbolAddress((void**)&xfp, g_xf);

    // Opt-in shared memory sizes
    const size_t smem_l0 = (size_t)(128 * 66 + 128 * 66 + 128 * 128 + 128 * 64 + 128) * 4;  // 166400
    const size_t smem_l1 = (size_t)(64 * 66 + 64 * 66 + 64 * 64 + 64 * 64 + 128) * 4;       // 67072
    const size_t smem_fc = (size_t)(256 * 66 + 256 * 64 + 128) * 4;                          // 133632
    cudaFuncSetAttribute(k_mlp<128, 128, 64>, cudaFuncAttributeMaxDynamicSharedMemorySize, (int)smem_l0);
    cudaFuncSetAttribute(k_mlp<64, 64, 64>, cudaFuncAttributeMaxDynamicSharedMemorySize, (int)smem_l1);
    cudaFuncSetAttribute(k_fc, cudaFuncAttributeMaxDynamicSharedMemorySize, (int)smem_fc);

    int nbWarpNode = (N * 32 + 255) / 256;  // warp-per-node grids
    int nbNodes = (N + 255) / 256;
    int nbEdges = (E + 255) / 256;
    int nbScan = (N + 1023) / 1024;
    if (nbScan > MAX_SCAN_BLOCKS) nbScan = MAX_SCAN_BLOCKS;
    int nbMlp = (N + 63) / 64;
    int nbApply = (N * 64 + 255) / 256;

    // ---- h0 + CSR build ----
    k_init<<<nbWarpNode, 256>>>(node_deg, node_lab, emb_deg, emb_lab, N);
    k_zero_deg<<<nbNodes, 256>>>(N);
    k_count<<<nbEdges, 256>>>(ei, E);
    k_scan1<<<nbScan, 1024>>>(N);
    k_scan2<<<1, 1>>>(nbScan);
    k_scan3<<<nbScan, 1024>>>(N);
    k_fill<<<nbEdges, 256>>>(ei, E);

    // ---- GIN layer 0 ----
    k_agg<128><<<nbWarpNode, 256>>>(h0p, aggp, N);
    k_zero_red<<<1, 128>>>();
    k_mlp<128, 128, 64><<<nbMlp, 256, smem_l0>>>(h0p, aggp, l0_w1, l0_b1, l0_w2, l0_b2,
                                                 l0_eps, x1p, N);
    k_bn_final<<<1, 64>>>(bn0_g, bn0_b, 1.0f / (float)N);
    k_apply<<<nbApply, 256>>>(x1p, h1p, N * 64);

    // ---- GIN layer 1 ----
    k_agg<64><<<nbWarpNode, 256>>>(h1p, aggp, N);
    k_zero_red<<<1, 128>>>();
    k_mlp<64, 64, 64><<<nbMlp, 256, smem_l1>>>(h1p, aggp, l1_w1, l1_b1, l1_w2, l1_b2,
                                               l1_eps, x2p, N);
    k_bn_final<<<1, 64>>>(bn1_g, bn1_b, 1.0f / (float)N);
    k_apply<<<nbApply, 256>>>(x2p, h2p, N * 64);

    // ---- FC head ----
    k_zero_red<<<1, 128>>>();
    k_fc<<<nbMlp, 256, smem_fc>>>(h0p, h1p, h2p, fc_w1, fc_b1, xfp, N);
    k_bn_final<<<1, 64>>>(fc_bn_g, fc_bn_b, 1.0f / (float)N);
    k_final<<<nbWarpNode, 256>>>(xfp, fc_w2, fc_b2, out, N);
}

// round 9
// speedup vs baseline: 1.7943x; 1.7943x over previous
#include <cuda_runtime.h>
#include <math.h>

// ---------------------------------------------------------------------------
// Problem constants (shapes fixed by the dataset)
// ---------------------------------------------------------------------------
#define NMAX 100000
#define EMAX 1200000
#define MAX_SCAN_BLOCKS 128   // ceil(NMAX/1024) = 98 < 128

typedef unsigned long long ULL;

// ---------------------------------------------------------------------------
// Scratch (static __device__ arrays; no allocations allowed)
// ---------------------------------------------------------------------------
__device__ float g_h0[NMAX * 128];   // embedding concat  [N,128]
__device__ float g_agg[NMAX * 128];  // aggregation buffer (layer1 uses 64)
__device__ float g_x1[NMAX * 64];    // layer0 pre-BN
__device__ float g_h1[NMAX * 64];    // layer0 output
__device__ float g_x2[NMAX * 64];    // layer1 pre-BN
__device__ float g_h2[NMAX * 64];    // layer1 output
__device__ float g_xf[NMAX * 64];    // fc pre-BN

__device__ int g_deg[NMAX];
__device__ int g_rowstart[NMAX];
__device__ int g_cursor[NMAX];
__device__ int g_csr[EMAX];
__device__ int g_blocksum[MAX_SCAN_BLOCKS];
__device__ int g_blockoff[MAX_SCAN_BLOCKS];

__device__ float g_red[128];  // [0..64) sum, [64..128) sumsq
__device__ float g_bnA[64];
__device__ float g_bnB[64];

// ---------------------------------------------------------------------------
// f32x2 helpers (sm_103a packed FFMA2 — only reachable via PTX)
// ---------------------------------------------------------------------------
__device__ __forceinline__ ULL pack2(float lo, float hi) {
    ULL r;
    asm("mov.b64 %0, {%1, %2};" : "=l"(r) : "r"(__float_as_uint(lo)), "r"(__float_as_uint(hi)));
    return r;
}
__device__ __forceinline__ void unpack2(ULL v, float& lo, float& hi) {
    unsigned int a, b;
    asm("mov.b64 {%0, %1}, %2;" : "=r"(a), "=r"(b) : "l"(v));
    lo = __uint_as_float(a);
    hi = __uint_as_float(b);
}
__device__ __forceinline__ ULL ffma2(ULL a, ULL b, ULL c) {
    ULL d;
    asm("fma.rn.f32x2 %0, %1, %2, %3;" : "=l"(d) : "l"(a), "l"(b), "l"(c));
    return d;
}
__device__ __forceinline__ float lrelu(float v) { return v > 0.f ? v : 0.01f * v; }

// ---------------------------------------------------------------------------
// Embedding concat: h0[node] = [emb_deg[deg], emb_lab[lab]]  (32 lanes/node)
// ---------------------------------------------------------------------------
__global__ void __launch_bounds__(256) k_init(const int* __restrict__ nd,
                                              const int* __restrict__ nl,
                                              const float* __restrict__ ed,
                                              const float* __restrict__ el, int N) {
    int g = blockIdx.x * 256 + threadIdx.x;
    int node = g >> 5, lane = g & 31;
    if (node >= N) return;
    float4 v;
    if (lane < 16)
        v = reinterpret_cast<const float4*>(ed + (size_t)nd[node] * 64)[lane];
    else
        v = reinterpret_cast<const float4*>(el + (size_t)nl[node] * 64)[lane - 16];
    reinterpret_cast<float4*>(g_h0 + (size_t)node * 128)[lane] = v;
}

// ---------------------------------------------------------------------------
// CSR build: zero deg -> count -> scan -> fill
// ---------------------------------------------------------------------------
__global__ void k_zero_deg(int N) {
    int i = blockIdx.x * blockDim.x + threadIdx.x;
    if (i < N) g_deg[i] = 0;
}
__global__ void k_count(const int* __restrict__ ei, int E) {
    int e = blockIdx.x * blockDim.x + threadIdx.x;
    if (e < E) atomicAdd(&g_deg[ei[E + e]], 1);
}
__global__ void __launch_bounds__(1024) k_scan1(int N) {
    __shared__ int s[1024];
    int t = threadIdx.x;
    int i = blockIdx.x * 1024 + t;
    int v = (i < N) ? g_deg[i] : 0;
    s[t] = v;
    __syncthreads();
#pragma unroll
    for (int off = 1; off < 1024; off <<= 1) {
        int a = (t >= off) ? s[t - off] : 0;
        __syncthreads();
        s[t] += a;
        __syncthreads();
    }
    if (i < N) g_rowstart[i] = s[t] - v;  // exclusive within block
    if (t == 1023) g_blocksum[blockIdx.x] = s[1023];
}
__global__ void k_scan2(int nb) {
    int acc = 0;
    for (int b = 0; b < nb; b++) {
        g_blockoff[b] = acc;
        acc += g_blocksum[b];
    }
}
__global__ void __launch_bounds__(1024) k_scan3(int N) {
    int i = blockIdx.x * 1024 + threadIdx.x;
    if (i < N) {
        int r = g_rowstart[i] + g_blockoff[blockIdx.x];
        g_rowstart[i] = r;
        g_cursor[i] = r;
    }
}
__global__ void k_fill(const int* __restrict__ ei, int E) {
    int e = blockIdx.x * blockDim.x + threadIdx.x;
    if (e < E) {
        int src = ei[e];
        int dst = ei[E + e];
        int p = atomicAdd(&g_cursor[dst], 1);
        g_csr[p] = src;
    }
}

// ---------------------------------------------------------------------------
// Segment-sum aggregation (warp per node, gather-based, unroll-4 for MLP)
// ---------------------------------------------------------------------------
template <int D>
__global__ void __launch_bounds__(256) k_agg(const float* __restrict__ hin,
                                             float* __restrict__ aggout, int N) {
    int g = blockIdx.x * 256 + threadIdx.x;
    int node = g >> 5, lane = g & 31;
    if (node >= N) return;
    int s = g_rowstart[node];
    int d = g_deg[node];
    if (D == 128) {
        float4 acc = make_float4(0.f, 0.f, 0.f, 0.f);
        int i = 0;
        for (; i + 4 <= d; i += 4) {
            int s0 = g_csr[s + i], s1 = g_csr[s + i + 1];
            int s2 = g_csr[s + i + 2], s3 = g_csr[s + i + 3];
            float4 r0 = reinterpret_cast<const float4*>(hin + (size_t)s0 * 128)[lane];
            float4 r1 = reinterpret_cast<const float4*>(hin + (size_t)s1 * 128)[lane];
            float4 r2 = reinterpret_cast<const float4*>(hin + (size_t)s2 * 128)[lane];
            float4 r3 = reinterpret_cast<const float4*>(hin + (size_t)s3 * 128)[lane];
            acc.x += r0.x + r1.x + r2.x + r3.x;
            acc.y += r0.y + r1.y + r2.y + r3.y;
            acc.z += r0.z + r1.z + r2.z + r3.z;
            acc.w += r0.w + r1.w + r2.w + r3.w;
        }
        for (; i < d; i++) {
            int src = g_csr[s + i];
            float4 r = reinterpret_cast<const float4*>(hin + (size_t)src * 128)[lane];
            acc.x += r.x; acc.y += r.y; acc.z += r.z; acc.w += r.w;
        }
        reinterpret_cast<float4*>(aggout + (size_t)node * 128)[lane] = acc;
    } else {
        float2 acc = make_float2(0.f, 0.f);
        int i = 0;
        for (; i + 4 <= d; i += 4) {
            int s0 = g_csr[s + i], s1 = g_csr[s + i + 1];
            int s2 = g_csr[s + i + 2], s3 = g_csr[s + i + 3];
            float2 r0 = reinterpret_cast<const float2*>(hin + (size_t)s0 * 64)[lane];
            float2 r1 = reinterpret_cast<const float2*>(hin + (size_t)s1 * 64)[lane];
            float2 r2 = reinterpret_cast<const float2*>(hin + (size_t)s2 * 64)[lane];
            float2 r3 = reinterpret_cast<const float2*>(hin + (size_t)s3 * 64)[lane];
            acc.x += r0.x + r1.x + r2.x + r3.x;
            acc.y += r0.y + r1.y + r2.y + r3.y;
        }
        for (; i < d; i++) {
            int src = g_csr[s + i];
            float2 r = reinterpret_cast<const float2*>(hin + (size_t)src * 64)[lane];
            acc.x += r.x; acc.y += r.y;
        }
        reinterpret_cast<float2*>(aggout + (size_t)node * 64)[lane] = acc;
    }
}

// ---------------------------------------------------------------------------
// BN reduction helpers
// ---------------------------------------------------------------------------
__global__ void k_zero_red() {
    if (threadIdx.x < 128) g_red[threadIdx.x] = 0.f;
}
__global__ void k_bn_final(const float* __restrict__ gam, const float* __restrict__ bet,
                           float invN) {
    int c = threadIdx.x;  // 64 threads
    float mean = g_red[c] * invN;
    float var = g_red[64 + c] * invN - mean * mean;
    float a = gam[c] * rsqrtf(var + 1e-5f);
    g_bnA[c] = a;
    g_bnB[c] = bet[c] - mean * a;
}
__global__ void __launch_bounds__(256) k_apply(const float* __restrict__ x,
                                               float* __restrict__ h, int total) {
    int i = blockIdx.x * 256 + threadIdx.x;
    if (i < total) {
        int c = i & 63;
        h[i] = lrelu(fmaf(x[i], g_bnA[c], g_bnB[c]));
    }
}

// ---------------------------------------------------------------------------
// Fused GIN MLP, channel-pair f32x2 design.
//   x = (1+eps)*h + agg ; hid = lrelu(x@W1+b1) ; out = hid@W2+b2 (+ BN sums)
// Block = 128 nodes, 256 threads (8 warps).
// Thread tile: 4 consecutive nodes x (D/8) consecutive channels per stage.
// Warp map: lane = cgrp*8 + ngrp  (4 channel-groups x 8 node-groups)
//           warp = chblk*4 + nodeblk (2 channel-halves x 4 node-blocks)
// Weights consumed directly as 8-byte (c,c+1) pairs — zero pack overhead.
// ---------------------------------------------------------------------------
template <int K, int H, int M>
__global__ void __launch_bounds__(256) k_mlp2(const float* __restrict__ hin,
                                              const float* __restrict__ agg,
                                              const float* __restrict__ W1,
                                              const float* __restrict__ b1,
                                              const float* __restrict__ W2,
                                              const float* __restrict__ b2,
                                              const float* __restrict__ epsp,
                                              float* __restrict__ xout, int N) {
    constexpr int TN = 128, TNp = 132;
    extern __shared__ float sm[];
    float* xs = sm;                 // [K][TNp], reused as hs [H][TNp] (H <= K)
    float* W1s = xs + K * TNp;      // [K][H]
    float* W2s = W1s + K * H;       // [H][M]
    float* sred = W2s + H * M;      // [2*M]

    const int tid = threadIdx.x;
    const int node0 = blockIdx.x * TN;
    const float eps1 = 1.0f + __ldg(epsp);

    for (int i = tid; i < K * H; i += 256) W1s[i] = W1[i];
    for (int i = tid; i < H * M; i += 256) W2s[i] = W2[i];
    if (tid < 2 * M) sred[tid] = 0.f;

    // ---- stage x transposed: xs[k][n] = (1+eps)*h[n][k] + agg[n][k] ----
    {
        int n = tid & 127;
        int half = tid >> 7;
        int node = node0 + n;
        bool ok = node < N;
        const float4* hp = reinterpret_cast<const float4*>(hin + (size_t)node * K);
        const float4* ap = reinterpret_cast<const float4*>(agg + (size_t)node * K);
        int k4b = half * (K / 8);
#pragma unroll
        for (int q = 0; q < K / 8; q++) {
            int k4 = k4b + q;
            float4 hv = ok ? hp[k4] : make_float4(0.f, 0.f, 0.f, 0.f);
            float4 av = ok ? ap[k4] : make_float4(0.f, 0.f, 0.f, 0.f);
            xs[(4 * k4 + 0) * TNp + n] = fmaf(eps1, hv.x, av.x);
            xs[(4 * k4 + 1) * TNp + n] = fmaf(eps1, hv.y, av.y);
            xs[(4 * k4 + 2) * TNp + n] = fmaf(eps1, hv.z, av.z);
            xs[(4 * k4 + 3) * TNp + n] = fmaf(eps1, hv.w, av.w);
        }
    }
    __syncthreads();

    const int w = tid >> 5, l = tid & 31;
    const int nodeblk = w & 3, chblk = w >> 2;
    const int cgrp = l >> 3, ngrp = l & 7;
    const int nb = nodeblk * 32 + ngrp * 4;  // 4 nodes [nb, nb+4)

    // ---- stage 1: x @ W1 + b1 -> lrelu -> hs ----
    constexpr int P1 = H / 16;  // channel pairs per thread
    {
        const int cb = chblk * (H / 2) + cgrp * (H / 8);
        ULL acc[4][P1];
#pragma unroll
        for (int j = 0; j < P1; j++) {
            ULL bb = pack2(__ldg(b1 + cb + 2 * j), __ldg(b1 + cb + 2 * j + 1));
#pragma unroll
            for (int p = 0; p < 4; p++) acc[p][j] = bb;
        }
#pragma unroll 2
        for (int k = 0; k < K; k++) {
            float4 av = *reinterpret_cast<const float4*>(xs + k * TNp + nb);
            ULL a0 = pack2(av.x, av.x), a1 = pack2(av.y, av.y);
            ULL a2 = pack2(av.z, av.z), a3 = pack2(av.w, av.w);
            const ULL* wp = reinterpret_cast<const ULL*>(W1s + k * H + cb);
#pragma unroll
            for (int j = 0; j < P1; j++) {
                ULL ww = wp[j];
                acc[0][j] = ffma2(a0, ww, acc[0][j]);
                acc[1][j] = ffma2(a1, ww, acc[1][j]);
                acc[2][j] = ffma2(a2, ww, acc[2][j]);
                acc[3][j] = ffma2(a3, ww, acc[3][j]);
            }
        }
        __syncthreads();  // all xs reads done before overwrite as hs
#pragma unroll
        for (int j = 0; j < P1; j++) {
            float lo[4], hi[4];
#pragma unroll
            for (int p = 0; p < 4; p++) unpack2(acc[p][j], lo[p], hi[p]);
            float4 vlo = make_float4(lrelu(lo[0]), lrelu(lo[1]), lrelu(lo[2]), lrelu(lo[3]));
            float4 vhi = make_float4(lrelu(hi[0]), lrelu(hi[1]), lrelu(hi[2]), lrelu(hi[3]));
            *reinterpret_cast<float4*>(xs + (cb + 2 * j) * TNp + nb) = vlo;
            *reinterpret_cast<float4*>(xs + (cb + 2 * j + 1) * TNp + nb) = vhi;
        }
    }
    __syncthreads();

    // ---- stage 2: hs @ W2 + b2 -> xout (+ BN partial sums) ----
    constexpr int P2 = M / 16;
    {
        const int cb = chblk * (M / 2) + cgrp * (M / 8);
        ULL acc[4][P2];
#pragma unroll
        for (int j = 0; j < P2; j++) {
            ULL bb = pack2(__ldg(b2 + cb + 2 * j), __ldg(b2 + cb + 2 * j + 1));
#pragma unroll
            for (int p = 0; p < 4; p++) acc[p][j] = bb;
        }
#pragma unroll 2
        for (int k = 0; k < H; k++) {
            float4 av = *reinterpret_cast<const float4*>(xs + k * TNp + nb);
            ULL a0 = pack2(av.x, av.x), a1 = pack2(av.y, av.y);
            ULL a2 = pack2(av.z, av.z), a3 = pack2(av.w, av.w);
            const ULL* wp = reinterpret_cast<const ULL*>(W2s + k * M + cb);
#pragma unroll
            for (int j = 0; j < P2; j++) {
                ULL ww = wp[j];
                acc[0][j] = ffma2(a0, ww, acc[0][j]);
                acc[1][j] = ffma2(a1, ww, acc[1][j]);
                acc[2][j] = ffma2(a2, ww, acc[2][j]);
                acc[3][j] = ffma2(a3, ww, acc[3][j]);
            }
        }
        float s[2 * P2], q[2 * P2];
#pragma unroll
        for (int c = 0; c < 2 * P2; c++) { s[c] = 0.f; q[c] = 0.f; }
#pragma unroll
        for (int p = 0; p < 4; p++) {
            int node = node0 + nb + p;
            if (node < N) {
                float v[2 * P2];
#pragma unroll
                for (int j = 0; j < P2; j++) unpack2(acc[p][j], v[2 * j], v[2 * j + 1]);
                *reinterpret_cast<float4*>(xout + (size_t)node * M + cb) =
                    make_float4(v[0], v[1], v[2], v[3]);
                *reinterpret_cast<float4*>(xout + (size_t)node * M + cb + 4) =
                    make_float4(v[4], v[5], v[6], v[7]);
#pragma unroll
                for (int c = 0; c < 2 * P2; c++) { s[c] += v[c]; q[c] += v[c] * v[c]; }
            }
        }
#pragma unroll
        for (int c = 0; c < 2 * P2; c++) {
            atomicAdd(&sred[cb + c], s[c]);
            atomicAdd(&sred[M + cb + c], q[c]);
        }
    }
    __syncthreads();
    if (tid < 2 * M) atomicAdd(&g_red[tid], sred[tid]);
}

// ---------------------------------------------------------------------------
// FC head GEMM: concat(h0,h1,h2) [256] @ fc_w1 [256,64] + b -> xf (+ BN sums)
// Same channel-pair tiling, single stage, K=256.
// ---------------------------------------------------------------------------
__global__ void __launch_bounds__(256) k_fc2(const float* __restrict__ h0,
                                             const float* __restrict__ h1,
                                             const float* __restrict__ h2,
                                             const float* __restrict__ W,
                                             const float* __restrict__ b,
                                             float* __restrict__ xout, int N) {
    constexpr int K = 256, M = 64, TN = 128, TNp = 132;
    extern __shared__ float sm[];
    float* xs = sm;               // [K][TNp]
    float* Ws = xs + K * TNp;     // [K][M]
    float* sred = Ws + K * M;     // [2*M]

    const int tid = threadIdx.x;
    const int node0 = blockIdx.x * TN;

    for (int i = tid; i < K * M; i += 256) Ws[i] = W[i];
    if (tid < 2 * M) sred[tid] = 0.f;

    // stage concat(h0,h1,h2) transposed
    {
        int n = tid & 127;
        int half = tid >> 7;
        int node = node0 + n;
        bool ok = node < N;
        const float4* p0 = reinterpret_cast<const float4*>(h0 + (size_t)node * 128);
        const float4* p1 = reinterpret_cast<const float4*>(h1 + (size_t)node * 64);
        const float4* p2 = reinterpret_cast<const float4*>(h2 + (size_t)node * 64);
        int k4b = half * 32;
#pragma unroll
        for (int q = 0; q < 32; q++) {
            int k4 = k4b + q;
            float4 v = make_float4(0.f, 0.f, 0.f, 0.f);
            if (ok) {
                if (k4 < 32) v = p0[k4];
                else if (k4 < 48) v = p1[k4 - 32];
                else v = p2[k4 - 48];
            }
            xs[(4 * k4 + 0) * TNp + n] = v.x;
            xs[(4 * k4 + 1) * TNp + n] = v.y;
            xs[(4 * k4 + 2) * TNp + n] = v.z;
            xs[(4 * k4 + 3) * TNp + n] = v.w;
        }
    }
    __syncthreads();

    const int w = tid >> 5, l = tid & 31;
    const int nodeblk = w & 3, chblk = w >> 2;
    const int cgrp = l >> 3, ngrp = l & 7;
    const int nb = nodeblk * 32 + ngrp * 4;
    constexpr int P = M / 16;  // 4 pairs = 8 channels per thread
    const int cb = chblk * (M / 2) + cgrp * (M / 8);

    ULL acc[4][P];
#pragma unroll
    for (int j = 0; j < P; j++) {
        ULL bb = pack2(__ldg(b + cb + 2 * j), __ldg(b + cb + 2 * j + 1));
#pragma unroll
        for (int p = 0; p < 4; p++) acc[p][j] = bb;
    }
#pragma unroll 2
    for (int k = 0; k < K; k++) {
        float4 av = *reinterpret_cast<const float4*>(xs + k * TNp + nb);
        ULL a0 = pack2(av.x, av.x), a1 = pack2(av.y, av.y);
        ULL a2 = pack2(av.z, av.z), a3 = pack2(av.w, av.w);
        const ULL* wp = reinterpret_cast<const ULL*>(Ws + k * M + cb);
#pragma unroll
        for (int j = 0; j < P; j++) {
            ULL ww = wp[j];
            acc[0][j] = ffma2(a0, ww, acc[0][j]);
            acc[1][j] = ffma2(a1, ww, acc[1][j]);
            acc[2][j] = ffma2(a2, ww, acc[2][j]);
            acc[3][j] = ffma2(a3, ww, acc[3][j]);
        }
    }
    float s[2 * P], q[2 * P];
#pragma unroll
    for (int c = 0; c < 2 * P; c++) { s[c] = 0.f; q[c] = 0.f; }
#pragma unroll
    for (int p = 0; p < 4; p++) {
        int node = node0 + nb + p;
        if (node < N) {
            float v[2 * P];
#pragma unroll
            for (int j = 0; j < P; j++) unpack2(acc[p][j], v[2 * j], v[2 * j + 1]);
            *reinterpret_cast<float4*>(xout + (size_t)node * M + cb) =
                make_float4(v[0], v[1], v[2], v[3]);
            *reinterpret_cast<float4*>(xout + (size_t)node * M + cb + 4) =
                make_float4(v[4], v[5], v[6], v[7]);
#pragma unroll
            for (int c = 0; c < 2 * P; c++) { s[c] += v[c]; q[c] += v[c] * v[c]; }
        }
    }
#pragma unroll
    for (int c = 0; c < 2 * P; c++) {
        atomicAdd(&sred[cb + c], s[c]);
        atomicAdd(&sred[M + cb + c], q[c]);
    }
    __syncthreads();
    if (tid < 2 * M) atomicAdd(&g_red[tid], sred[tid]);
}

// ---------------------------------------------------------------------------
// Final: BN-apply + lrelu + dot(fc_w2) + sigmoid  (warp per node)
// ---------------------------------------------------------------------------
__global__ void __launch_bounds__(256) k_final(const float* __restrict__ xf,
                                               const float* __restrict__ w2,
                                               const float* __restrict__ b2,
                                               float* __restrict__ out, int N) {
    int g = blockIdx.x * 256 + threadIdx.x;
    int node = g >> 5, lane = g & 31;
    if (node >= N) return;
    int c0 = lane, c1 = lane + 32;
    float v0 = lrelu(fmaf(xf[(size_t)node * 64 + c0], g_bnA[c0], g_bnB[c0]));
    float v1 = lrelu(fmaf(xf[(size_t)node * 64 + c1], g_bnA[c1], g_bnB[c1]));
    float p = v0 * w2[c0] + v1 * w2[c1];
#pragma unroll
    for (int o = 16; o > 0; o >>= 1) p += __shfl_xor_sync(0xffffffffu, p, o);
    if (lane == 0) out[node] = 1.0f / (1.0f + expf(-(p + b2[0])));
}

// ---------------------------------------------------------------------------
// Launch
// ---------------------------------------------------------------------------
extern "C" void kernel_launch(void* const* d_in, const int* in_sizes, int n_in,
                              void* d_out, int out_size) {
    const int* node_deg = (const int*)d_in[0];
    const int* node_lab = (const int*)d_in[1];
    const int* ei       = (const int*)d_in[2];
    const float* emb_deg = (const float*)d_in[3];
    const float* emb_lab = (const float*)d_in[4];
    const float* l0_w1 = (const float*)d_in[5];
    const float* l0_b1 = (const float*)d_in[6];
    const float* l0_w2 = (const float*)d_in[7];
    const float* l0_b2 = (const float*)d_in[8];
    const float* l0_eps = (const float*)d_in[9];
    const float* bn0_g = (const float*)d_in[10];
    const float* bn0_b = (const float*)d_in[11];
    const float* l1_w1 = (const float*)d_in[12];
    const float* l1_b1 = (const float*)d_in[13];
    const float* l1_w2 = (const float*)d_in[14];
    const float* l1_b2 = (const float*)d_in[15];
    const float* l1_eps = (const float*)d_in[16];
    const float* bn1_g = (const float*)d_in[17];
    const float* bn1_b = (const float*)d_in[18];
    const float* fc_w1 = (const float*)d_in[19];
    const float* fc_b1 = (const float*)d_in[20];
    const float* fc_bn_g = (const float*)d_in[21];
    const float* fc_bn_b = (const float*)d_in[22];
    const float* fc_w2 = (const float*)d_in[23];
    const float* fc_b2 = (const float*)d_in[24];
    float* out = (float*)d_out;

    int N = in_sizes[0];
    int E = in_sizes[2] / 2;
    if (N > NMAX) N = NMAX;
    if (E > EMAX) E = EMAX;

    float *h0p, *aggp, *x1p, *h1p, *x2p, *h2p, *xfp;
    cudaGetSymbolAddress((void**)&h0p, g_h0);
    cudaGetSymbolAddress((void**)&aggp, g_agg);
    cudaGetSymbolAddress((void**)&x1p, g_x1);
    cudaGetSymbolAddress((void**)&h1p, g_h1);
    cudaGetSymbolAddress((void**)&x2p, g_x2);
    cudaGetSymbolAddress((void**)&h2p, g_h2);
    cudaGetSymbolAddress((void**)&xfp, g_xf);

    // smem: xs[K][132] + W1[K][H] + W2[H][M] + sred[2M]
    const size_t smem_l0 = (size_t)(128 * 132 + 128 * 128 + 128 * 64 + 128) * 4;  // 166400
    const size_t smem_l1 = (size_t)(64 * 132 + 64 * 64 + 64 * 64 + 128) * 4;      //  67072
    const size_t smem_fc = (size_t)(256 * 132 + 256 * 64 + 128) * 4;              // 201216
    cudaFuncSetAttribute(k_mlp2<128, 128, 64>, cudaFuncAttributeMaxDynamicSharedMemorySize, (int)smem_l0);
    cudaFuncSetAttribute(k_mlp2<64, 64, 64>, cudaFuncAttributeMaxDynamicSharedMemorySize, (int)smem_l1);
    cudaFuncSetAttribute(k_fc2, cudaFuncAttributeMaxDynamicSharedMemorySize, (int)smem_fc);

    int nbWarpNode = (N * 32 + 255) / 256;
    int nbNodes = (N + 255) / 256;
    int nbEdges = (E + 255) / 256;
    int nbScan = (N + 1023) / 1024;
    if (nbScan > MAX_SCAN_BLOCKS) nbScan = MAX_SCAN_BLOCKS;
    int nbMlp = (N + 127) / 128;
    int nbApply = (N * 64 + 255) / 256;

    // ---- h0 + CSR build ----
    k_init<<<nbWarpNode, 256>>>(node_deg, node_lab, emb_deg, emb_lab, N);
    k_zero_deg<<<nbNodes, 256>>>(N);
    k_count<<<nbEdges, 256>>>(ei, E);
    k_scan1<<<nbScan, 1024>>>(N);
    k_scan2<<<1, 1>>>(nbScan);
    k_scan3<<<nbScan, 1024>>>(N);
    k_fill<<<nbEdges, 256>>>(ei, E);

    // ---- GIN layer 0 ----
    k_agg<128><<<nbWarpNode, 256>>>(h0p, aggp, N);
    k_zero_red<<<1, 128>>>();
    k_mlp2<128, 128, 64><<<nbMlp, 256, smem_l0>>>(h0p, aggp, l0_w1, l0_b1, l0_w2, l0_b2,
                                                  l0_eps, x1p, N);
    k_bn_final<<<1, 64>>>(bn0_g, bn0_b, 1.0f / (float)N);
    k_apply<<<nbApply, 256>>>(x1p, h1p, N * 64);

    // ---- GIN layer 1 ----
    k_agg<64><<<nbWarpNode, 256>>>(h1p, aggp, N);
    k_zero_red<<<1, 128>>>();
    k_mlp2<64, 64, 64><<<nbMlp, 256, smem_l1>>>(h1p, aggp, l1_w1, l1_b1, l1_w2, l1_b2,
                                                l1_eps, x2p, N);
    k_bn_final<<<1, 64>>>(bn1_g, bn1_b, 1.0f / (float)N);
    k_apply<<<nbApply, 256>>>(x2p, h2p, N * 64);

    // ---- FC head ----
    k_zero_red<<<1, 128>>>();
    k_fc2<<<nbMlp, 256, smem_fc>>>(h0p, h1p, h2p, fc_w1, fc_b1, xfp, N);
    k_bn_final<<<1, 64>>>(fc_bn_g, fc_bn_b, 1.0f / (float)N);
    k_final<<<nbWarpNode, 256>>>(xfp, fc_w2, fc_b2, out, N);
}